// round 1
// baseline (speedup 1.0000x reference)
#include <cuda_runtime.h>
#include <cuda_bf16.h>

// Problem constants: I, J are [B=2, 1, D=192, H=192, W=192] fp32.
#define Bv   2
#define Dv   192
#define Hv   192
#define Wv   192
#define HWv  (Hv * Wv)              // 36864
#define DHWv (Dv * Hv * Wv)         // 7077888
#define Nv   (Bv * DHWv)            // 14155776
#define K_SUM 729.0f

// Scratch: 5 channels (I_sum, J_sum, II_sum, JJ_sum, IJ_sum) x N, two buffers.
__device__ float g_bufA[5u * (size_t)Nv];
__device__ float g_bufB[5u * (size_t)Nv];
__device__ double g_acc;

__global__ void zero_acc_k() { g_acc = 0.0; }

// ---------------------------------------------------------------------------
// Pass 1: pointwise products + 9-tap box sum along W (contiguous axis).
// One block per (b,d,h) line of 192; 192 threads.
// ---------------------------------------------------------------------------
__global__ void __launch_bounds__(192) pass1_k(const float* __restrict__ I,
                                               const float* __restrict__ J) {
    __shared__ float4 sA[Wv];   // (I, I*I, J*J, I*J)
    __shared__ float  sJ[Wv];
    const int w = threadIdx.x;
    const size_t base = (size_t)blockIdx.x * Wv;

    float iv = I[base + w];
    float jv = J[base + w];
    sA[w] = make_float4(iv, iv * iv, jv * jv, iv * jv);
    sJ[w] = jv;
    __syncthreads();

    float si = 0.f, sii = 0.f, sjj = 0.f, sij = 0.f, sj = 0.f;
#pragma unroll
    for (int k = -4; k <= 4; k++) {
        int ww = w + k;
        if (ww >= 0 && ww < Wv) {
            float4 v = sA[ww];
            si  += v.x;
            sii += v.y;
            sjj += v.z;
            sij += v.w;
            sj  += sJ[ww];
        }
    }
    const size_t o = base + w;
    g_bufA[0 * (size_t)Nv + o] = si;
    g_bufA[1 * (size_t)Nv + o] = sj;
    g_bufA[2 * (size_t)Nv + o] = sii;
    g_bufA[3 * (size_t)Nv + o] = sjj;
    g_bufA[4 * (size_t)Nv + o] = sij;
}

// ---------------------------------------------------------------------------
// Pass 2: 9-tap box sum along H via per-thread streaming window.
// Ring buffer (5 channels x 9 taps) kept in registers via static indexing.
// Grid: (B*D slabs) x (2 H-chunks of 96). 192 threads (one per w).
// ---------------------------------------------------------------------------
#define HCH 96
__global__ void __launch_bounds__(192) pass2_k() {
    const int bid   = blockIdx.x;
    const int chunk = bid & 1;
    const int slab  = bid >> 1;          // 0 .. B*D-1
    const int w     = threadIdx.x;
    const int h0    = chunk * HCH;
    const size_t sbase = (size_t)slab * HWv + w;

    float ring[5][9];
    float sum[5];
#pragma unroll
    for (int c = 0; c < 5; c++) sum[c] = 0.f;

    // Prefill: ring[c][m] = in[h0-4+m] (zero outside). Window sum = taps m=4..8.
#pragma unroll
    for (int m = 0; m < 9; m++) {
        int h = h0 - 4 + m;
        bool ok = (h >= 0) && (h < Hv);
#pragma unroll
        for (int c = 0; c < 5; c++) {
            float v = ok ? g_bufA[(size_t)c * Nv + sbase + (size_t)h * Wv] : 0.f;
            ring[c][m] = v;
            if (m >= 4) sum[c] += v;
        }
    }

    for (int tb = 0; tb < HCH; tb += 9) {
#pragma unroll
        for (int r = 0; r < 9; r++) {
            int t = tb + r;
            if (t < HCH) {
                int h = h0 + t;
                size_t o = sbase + (size_t)h * Wv;
                int hl = h + 5;
                bool ok = (hl < Hv);
#pragma unroll
                for (int c = 0; c < 5; c++) {
                    g_bufB[(size_t)c * Nv + o] = sum[c];
                    float lv = ok ? g_bufA[(size_t)c * Nv + sbase + (size_t)hl * Wv] : 0.f;
                    sum[c] += lv - ring[c][r];
                    ring[c][r] = lv;
                }
            }
        }
    }
}

// ---------------------------------------------------------------------------
// Pass 3: 9-tap box sum along D (streaming window) + NCC combine + reduction.
// Grid: (B*H rows) x (2 D-chunks of 96). 192 threads (one per w).
// ---------------------------------------------------------------------------
#define DCH 96
__global__ void __launch_bounds__(192) pass3_k(const float* __restrict__ I,
                                               const float* __restrict__ J) {
    const int bid   = blockIdx.x;
    const int chunk = bid & 1;
    const int bh    = bid >> 1;          // 0 .. B*H-1
    const int b     = bh / Hv;
    const int h     = bh % Hv;
    const int w     = threadIdx.x;
    const int d0    = chunk * DCH;
    const size_t cbase = (size_t)b * DHWv + (size_t)h * Wv + w;  // at d=0

    float ring[5][9];
    float sum[5];
#pragma unroll
    for (int c = 0; c < 5; c++) sum[c] = 0.f;

#pragma unroll
    for (int m = 0; m < 9; m++) {
        int d = d0 - 4 + m;
        bool ok = (d >= 0) && (d < Dv);
#pragma unroll
        for (int c = 0; c < 5; c++) {
            float v = ok ? g_bufB[(size_t)c * Nv + cbase + (size_t)d * HWv] : 0.f;
            ring[c][m] = v;
            if (m >= 4) sum[c] += v;
        }
    }

    float local = 0.f;
    const float inv_k = 1.0f / K_SUM;

    for (int tb = 0; tb < DCH; tb += 9) {
#pragma unroll
        for (int r = 0; r < 9; r++) {
            int t = tb + r;
            if (t < DCH) {
                int d = d0 + t;
                size_t o = cbase + (size_t)d * HWv;

                float Is  = sum[0];
                float Js  = sum[1];
                float IIs = sum[2];
                float JJs = sum[3];
                float IJs = sum[4];

                float iv = I[o];
                float jv = J[o];
                float iu = iv * inv_k;
                float ju = jv * inv_k;

                float cross = IJs - Is * ju - Js * iu + iu * ju * K_SUM;
                float ivar  = IIs - 2.f * Is * iu + iu * iu * K_SUM;
                float jvar  = JJs - 2.f * Js * ju + ju * ju * K_SUM;

                local += (cross * cross) / (ivar * jvar + 1e-5f);

                int dl = d + 5;
                bool ok = (dl < Dv);
#pragma unroll
                for (int c = 0; c < 5; c++) {
                    float lv = ok ? g_bufB[(size_t)c * Nv + cbase + (size_t)dl * HWv] : 0.f;
                    sum[c] += lv - ring[c][r];
                    ring[c][r] = lv;
                }
            }
        }
    }

    // Reduce 192 threads -> 1 double atomic.
    __shared__ float red[6];
    float v = local;
#pragma unroll
    for (int off = 16; off > 0; off >>= 1)
        v += __shfl_down_sync(0xffffffffu, v, off);
    if ((w & 31) == 0) red[w >> 5] = v;
    __syncthreads();
    if (w == 0) {
        float s = 0.f;
#pragma unroll
        for (int i = 0; i < 6; i++) s += red[i];
        atomicAdd(&g_acc, (double)s);
    }
}

__global__ void finalize_k(float* __restrict__ out) {
    out[0] = (float)(-g_acc / (double)Nv);
}

extern "C" void kernel_launch(void* const* d_in, const int* in_sizes, int n_in,
                              void* d_out, int out_size) {
    const float* I = (const float*)d_in[0];
    const float* J = (const float*)d_in[1];
    float* out = (float*)d_out;

    zero_acc_k<<<1, 1>>>();
    pass1_k<<<Bv * Dv * Hv, 192>>>(I, J);                 // 73728 blocks
    pass2_k<<<Bv * Dv * 2, 192>>>();                      // 768 blocks
    pass3_k<<<Bv * Hv * 2, 192>>>(I, J);                  // 768 blocks
    finalize_k<<<1, 1>>>(out);
}

// round 2
// speedup vs baseline: 1.7233x; 1.7233x over previous
#include <cuda_runtime.h>
#include <cuda_bf16.h>

// Problem constants: I, J are [B=2, 1, D=192, H=192, W=192] fp32.
#define Bv   2
#define Dv   192
#define Hv   192
#define Wv   192
#define W4v  (Wv / 4)               // 48 float4 lanes per row
#define HWv  (Hv * Wv)              // 36864
#define DHWv (Dv * Hv * Wv)         // 7077888
#define Nv   (Bv * DHWv)            // 14155776
#define K_SUM 729.0f

// Scratch: 5 channels (I_sum, J_sum, II_sum, JJ_sum, IJ_sum) x N, two buffers.
__device__ __align__(16) float g_bufA[5u * (size_t)Nv];
__device__ __align__(16) float g_bufB[5u * (size_t)Nv];
__device__ double g_acc;

__global__ void zero_acc_k() { g_acc = 0.0; }

static __device__ __forceinline__ float4 f4add(float4 a, float4 b) {
    return make_float4(a.x + b.x, a.y + b.y, a.z + b.z, a.w + b.w);
}
static __device__ __forceinline__ float4 f4sub(float4 a, float4 b) {
    return make_float4(a.x - b.x, a.y - b.y, a.z - b.z, a.w - b.w);
}

// ---------------------------------------------------------------------------
// Pass 1: pointwise products + 9-tap box sum along W (contiguous axis).
// Block = 192 threads = 4 rows x 48 float4 lanes. Sliding-window via smem.
// ---------------------------------------------------------------------------
__global__ void __launch_bounds__(192) pass1_k(const float* __restrict__ I,
                                               const float* __restrict__ J) {
    __shared__ float sm[5][4][Wv];
    const int tid  = threadIdx.x;
    const int tr   = tid / 48;          // row within block (0..3)
    const int lane = tid % 48;          // float4 lane
    const size_t rowbase = ((size_t)blockIdx.x * 4 + tr) * (size_t)Wv;
    const int w0 = 4 * lane;

    float4 iv = *(const float4*)(I + rowbase + w0);
    float4 jv = *(const float4*)(J + rowbase + w0);

    ((float4*)sm[0][tr])[lane] = iv;
    ((float4*)sm[1][tr])[lane] = jv;
    ((float4*)sm[2][tr])[lane] = make_float4(iv.x*iv.x, iv.y*iv.y, iv.z*iv.z, iv.w*iv.w);
    ((float4*)sm[3][tr])[lane] = make_float4(jv.x*jv.x, jv.y*jv.y, jv.z*jv.z, jv.w*jv.w);
    ((float4*)sm[4][tr])[lane] = make_float4(iv.x*jv.x, iv.y*jv.y, iv.z*jv.z, iv.w*jv.w);
    __syncthreads();

#pragma unroll
    for (int c = 0; c < 5; c++) {
        const float* row = sm[c][tr];
        float s = 0.f;
#pragma unroll
        for (int k = -4; k <= 4; k++) {
            int ww = w0 + k;
            if (ww >= 0 && ww < Wv) s += row[ww];
        }
        float4 o;
        o.x = s;
        // slide: output w uses window [w-4, w+4]
        {   int a = w0 + 5, r = w0 - 4;
            s += ((a < Wv) ? row[a] : 0.f) - ((r >= 0) ? row[r] : 0.f); o.y = s; }
        {   int a = w0 + 6, r = w0 - 3;
            s += ((a < Wv) ? row[a] : 0.f) - ((r >= 0) ? row[r] : 0.f); o.z = s; }
        {   int a = w0 + 7, r = w0 - 2;
            s += ((a < Wv) ? row[a] : 0.f) - ((r >= 0) ? row[r] : 0.f); o.w = s; }
        *(float4*)(g_bufA + (size_t)c * Nv + rowbase + w0) = o;
    }
}

// ---------------------------------------------------------------------------
// Pass 2: 9-tap box sum along H. One block per (slab, channel); threads are
// 48 float4 lanes x 4 H-sub-chunks of 48. Register ring of float4[9].
// FULL 9-tap prefill (fixes round-1 window bug).
// ---------------------------------------------------------------------------
__global__ void __launch_bounds__(192) pass2_k() {
    const int bid  = blockIdx.x;        // 0 .. Bv*Dv*5 - 1
    const int ch   = bid % 5;
    const int slab = bid / 5;           // (b, d)
    const int lane = threadIdx.x % 48;
    const int sub  = threadIdx.x / 48;  // 0..3
    const int h0   = sub * 48;

    const float4* __restrict__ src =
        (const float4*)(g_bufA + (size_t)ch * Nv + (size_t)slab * HWv);
    float4* __restrict__ dst =
        (float4*)(g_bufB + (size_t)ch * Nv + (size_t)slab * HWv);

    float4 ring[9];
    float4 sum = make_float4(0.f, 0.f, 0.f, 0.f);
#pragma unroll
    for (int m = 0; m < 9; m++) {       // rows h0-4 .. h0+4 (all 9 taps)
        int h = h0 - 4 + m;
        float4 v = make_float4(0.f, 0.f, 0.f, 0.f);
        if (h >= 0 && h < Hv) v = src[h * W4v + lane];
        ring[m] = v;
        sum = f4add(sum, v);
    }
#pragma unroll
    for (int t = 0; t < 48; t++) {
        int h = h0 + t;
        dst[h * W4v + lane] = sum;      // window [h-4, h+4]
        int hl = h + 5;
        float4 v = make_float4(0.f, 0.f, 0.f, 0.f);
        if (hl < Hv) v = src[hl * W4v + lane];
        sum = f4add(sum, f4sub(v, ring[t % 9]));
        ring[t % 9] = v;
    }
}

// ---------------------------------------------------------------------------
// Pass 3: 9-tap box sum along D + NCC combine + reduction.
// No register ring: trailing tap is re-loaded (guaranteed L2/L1 hit — the
// lag window per block is ~31KB). 5 sums in registers -> low reg pressure,
// 1536 blocks x 192 threads.
// ---------------------------------------------------------------------------
__global__ void __launch_bounds__(192) pass3_k(const float* __restrict__ I,
                                               const float* __restrict__ J) {
    const int bid   = blockIdx.x;       // Bv*Hv*4
    const int chunk = bid & 3;
    const int bh    = bid >> 2;
    const int b     = bh / Hv;
    const int h     = bh % Hv;
    const int w     = threadIdx.x;
    const int d0    = chunk * 48;
    const size_t cbase = (size_t)b * DHWv + (size_t)h * Wv + w;

    const float* __restrict__ c0 = g_bufB;
    const float* __restrict__ c1 = g_bufB + (size_t)Nv;
    const float* __restrict__ c2 = g_bufB + 2 * (size_t)Nv;
    const float* __restrict__ c3 = g_bufB + 3 * (size_t)Nv;
    const float* __restrict__ c4 = g_bufB + 4 * (size_t)Nv;

    float s0 = 0.f, s1 = 0.f, s2 = 0.f, s3 = 0.f, s4 = 0.f;
#pragma unroll
    for (int m = 0; m < 8; m++) {       // rows d0-4 .. d0+3
        int d = d0 - 4 + m;
        if (d >= 0) {
            size_t o = cbase + (size_t)d * HWv;
            s0 += c0[o]; s1 += c1[o]; s2 += c2[o]; s3 += c3[o]; s4 += c4[o];
        }
    }

    float local = 0.f;
    const float inv_k = 1.0f / K_SUM;

#pragma unroll 6
    for (int t = 0; t < 48; t++) {
        int d = d0 + t;
        size_t o = cbase + (size_t)d * HWv;

        int dl = d + 4;                 // leading edge
        if (dl < Dv) {
            size_t ol = o + 4 * (size_t)HWv;
            s0 += c0[ol]; s1 += c1[ol]; s2 += c2[ol]; s3 += c3[ol]; s4 += c4[ol];
        }

        float iv = I[o];
        float jv = J[o];
        float iu = iv * inv_k;
        float ju = jv * inv_k;

        float cross = s4 - s0 * ju - s1 * iu + iu * ju * K_SUM;
        float ivar  = s2 - 2.f * s0 * iu + iu * iu * K_SUM;
        float jvar  = s3 - 2.f * s1 * ju + ju * ju * K_SUM;

        local += (cross * cross) / (ivar * jvar + 1e-5f);

        int dt = d - 4;                 // trailing edge (cache-hit reload)
        if (dt >= 0) {
            size_t ot = o - 4 * (size_t)HWv;
            s0 -= c0[ot]; s1 -= c1[ot]; s2 -= c2[ot]; s3 -= c3[ot]; s4 -= c4[ot];
        }
    }

    // Reduce 192 threads -> 1 double atomic.
    __shared__ float red[6];
    float v = local;
#pragma unroll
    for (int off = 16; off > 0; off >>= 1)
        v += __shfl_down_sync(0xffffffffu, v, off);
    if ((w & 31) == 0) red[w >> 5] = v;
    __syncthreads();
    if (w == 0) {
        float s = 0.f;
#pragma unroll
        for (int i = 0; i < 6; i++) s += red[i];
        atomicAdd(&g_acc, (double)s);
    }
}

__global__ void finalize_k(float* __restrict__ out) {
    out[0] = (float)(-g_acc / (double)Nv);
}

extern "C" void kernel_launch(void* const* d_in, const int* in_sizes, int n_in,
                              void* d_out, int out_size) {
    const float* I = (const float*)d_in[0];
    const float* J = (const float*)d_in[1];
    float* out = (float*)d_out;

    zero_acc_k<<<1, 1>>>();
    pass1_k<<<Bv * Dv * Hv / 4, 192>>>(I, J);   // 18432 blocks
    pass2_k<<<Bv * Dv * 5, 192>>>();            // 1920 blocks
    pass3_k<<<Bv * Hv * 4, 192>>>(I, J);        // 1536 blocks
    finalize_k<<<1, 1>>>(out);
}

// round 3
// speedup vs baseline: 2.1805x; 1.2653x over previous
#include <cuda_runtime.h>
#include <cuda_bf16.h>

// Problem constants: I, J are [B=2, 1, D=192, H=192, W=192] fp32.
#define Bv   2
#define Dv   192
#define Hv   192
#define Wv   192
#define W4v  (Wv / 4)               // 48 float4 lanes per row
#define HWv  (Hv * Wv)              // 36864
#define DHWv (Dv * Hv * Wv)         // 7077888
#define Nv   (Bv * DHWv)            // 14155776
#define K_SUM 729.0f

#define HT     16                   // output H rows per p12 block
#define HTILES (Hv / HT)            // 12
#define HROWS  (HT + 8)             // 24 input rows incl. halo

// Scratch: 5 channels (I_sum, J_sum, II_sum, JJ_sum, IJ_sum) x N (HW-summed).
__device__ __align__(16) float g_bufB[5u * (size_t)Nv];
__device__ double g_acc;

__global__ void zero_acc_k() { g_acc = 0.0; }

static __device__ __forceinline__ float4 f4z() { return make_float4(0.f, 0.f, 0.f, 0.f); }

// Sliding 9-tap sums for 4 consecutive outputs from a 12-float window.
// p[m] = value at w0-4+m. out.x = window [w0-4, w0+4], etc.
static __device__ __forceinline__ float4 slide9(const float p[12]) {
    float s = p[0] + p[1] + p[2] + p[3] + p[4] + p[5] + p[6] + p[7] + p[8];
    float4 o;
    o.x = s;
    s += p[9]  - p[0]; o.y = s;
    s += p[10] - p[1]; o.z = s;
    s += p[11] - p[2]; o.w = s;
    return o;
}

// ---------------------------------------------------------------------------
// Fused pass: products + W box-sum + H box-sum, one DRAM round trip.
// Block = 192 threads (4 row-slots x 48 float4 lanes). One block per
// (b, d, H-tile of 16). Dynamic smem: ws[5][24][192] + sI[4][192] + sJ[4][192].
// ---------------------------------------------------------------------------
__global__ void __launch_bounds__(192) p12_k(const float* __restrict__ I,
                                             const float* __restrict__ J) {
    extern __shared__ float sm[];
    float* ws = sm;                          // [5][HROWS][Wv]
    float* sI = sm + 5 * HROWS * Wv;         // [4][Wv]
    float* sJ = sI + 4 * Wv;                 // [4][Wv]

    const int tid  = threadIdx.x;
    const int tr   = tid / 48;               // row slot (0..3)
    const int lane = tid % 48;               // float4 lane
    const int w0   = 4 * lane;
    const int tile = blockIdx.x % HTILES;
    const int slab = blockIdx.x / HTILES;    // b*Dv + d
    const int h0   = tile * HT;
    const size_t sbase = (size_t)slab * HWv;

    // Preload group 0 (input rows h0-4+tr).
    float4 iv, jv;
    {
        int h_in = h0 - 4 + tr;
        bool ok = (h_in >= 0) && (h_in < Hv);
        iv = ok ? *(const float4*)(I + sbase + (size_t)h_in * Wv + w0) : f4z();
        jv = ok ? *(const float4*)(J + sbase + (size_t)h_in * Wv + w0) : f4z();
    }

    // Phase A: 6 groups of 4 rows -> W box-sums of 5 channels into ws.
    for (int g = 0; g < 6; g++) {
        ((float4*)(sI + tr * Wv))[lane] = iv;
        ((float4*)(sJ + tr * Wv))[lane] = jv;
        __syncthreads();

        // Prefetch next group while this one computes.
        float4 niv = f4z(), njv = f4z();
        if (g < 5) {
            int h_in = h0 - 4 + (g + 1) * 4 + tr;
            if (h_in >= 0 && h_in < Hv) {
                niv = *(const float4*)(I + sbase + (size_t)h_in * Wv + w0);
                njv = *(const float4*)(J + sbase + (size_t)h_in * Wv + w0);
            }
        }

        // 12-float windows from smem (float4 reads: conflict-free).
        const float4* rI = (const float4*)(sI + tr * Wv);
        const float4* rJ = (const float4*)(sJ + tr * Wv);
        float4 a  = (lane > 0)  ? rI[lane - 1] : f4z();
        float4 b  = rI[lane];
        float4 c  = (lane < 47) ? rI[lane + 1] : f4z();
        float4 aj = (lane > 0)  ? rJ[lane - 1] : f4z();
        float4 bj = rJ[lane];
        float4 cj = (lane < 47) ? rJ[lane + 1] : f4z();

        float Iw[12] = {a.x, a.y, a.z, a.w, b.x, b.y, b.z, b.w, c.x, c.y, c.z, c.w};
        float Jw[12] = {aj.x, aj.y, aj.z, aj.w, bj.x, bj.y, bj.z, bj.w, cj.x, cj.y, cj.z, cj.w};

        const int r = g * 4 + tr;            // input row index (0..23)
        float4* wrow;

        wrow = (float4*)(ws + (0 * HROWS + r) * Wv + w0);
        *wrow = slide9(Iw);
        wrow = (float4*)(ws + (1 * HROWS + r) * Wv + w0);
        *wrow = slide9(Jw);
        {
            float t[12];
#pragma unroll
            for (int k = 0; k < 12; k++) t[k] = Iw[k] * Iw[k];
            wrow = (float4*)(ws + (2 * HROWS + r) * Wv + w0);
            *wrow = slide9(t);
#pragma unroll
            for (int k = 0; k < 12; k++) t[k] = Jw[k] * Jw[k];
            wrow = (float4*)(ws + (3 * HROWS + r) * Wv + w0);
            *wrow = slide9(t);
#pragma unroll
            for (int k = 0; k < 12; k++) t[k] = Iw[k] * Jw[k];
            wrow = (float4*)(ws + (4 * HROWS + r) * Wv + w0);
            *wrow = slide9(t);
        }
        __syncthreads();
        iv = niv; jv = njv;
    }

    // Phase B: H box-sum (9 rows) over ws, 4 output rows per thread slot.
    const int rg = tr;                       // output row group (0..3)
#pragma unroll
    for (int ch = 0; ch < 5; ch++) {
        const float4* wsc = (const float4*)(ws + ch * HROWS * Wv);
        float4 s = f4z();
#pragma unroll
        for (int m = 0; m < 9; m++) {
            float4 v = wsc[(rg * 4 + m) * W4v + lane];
            s.x += v.x; s.y += v.y; s.z += v.z; s.w += v.w;
        }
#pragma unroll
        for (int t = 0; t < 4; t++) {
            int h = h0 + rg * 4 + t;
            *(float4*)(g_bufB + (size_t)ch * Nv + sbase + (size_t)h * Wv + w0) = s;
            if (t < 3) {
                float4 add = wsc[(rg * 4 + t + 9) * W4v + lane];
                float4 sub = wsc[(rg * 4 + t) * W4v + lane];
                s.x += add.x - sub.x; s.y += add.y - sub.y;
                s.z += add.z - sub.z; s.w += add.w - sub.w;
            }
        }
    }
}

// ---------------------------------------------------------------------------
// Pass 3: 9-tap box sum along D + NCC combine + reduction.
// Trailing tap comes from an 8-slot smem ring (per-thread private columns),
// so DRAM traffic is exactly 5 leading channels + I,J.
// ---------------------------------------------------------------------------
__global__ void __launch_bounds__(192) pass3_k(const float* __restrict__ I,
                                               const float* __restrict__ J) {
    __shared__ float ring[5][8][192];

    const int bid   = blockIdx.x;            // Bv*Hv*4
    const int chunk = bid & 3;
    const int bh    = bid >> 2;
    const int b     = bh / Hv;
    const int h     = bh % Hv;
    const int w     = threadIdx.x;
    const int d0    = chunk * 48;
    const size_t cbase = (size_t)b * DHWv + (size_t)h * Wv + w;

    const float* __restrict__ c0 = g_bufB;
    const float* __restrict__ c1 = g_bufB + (size_t)Nv;
    const float* __restrict__ c2 = g_bufB + 2 * (size_t)Nv;
    const float* __restrict__ c3 = g_bufB + 3 * (size_t)Nv;
    const float* __restrict__ c4 = g_bufB + 4 * (size_t)Nv;

    float s0 = 0.f, s1 = 0.f, s2 = 0.f, s3 = 0.f, s4 = 0.f;
#pragma unroll
    for (int m = 0; m < 8; m++) {            // planes d0-4 .. d0+3
        int d = d0 - 4 + m;
        float v0 = 0.f, v1 = 0.f, v2 = 0.f, v3 = 0.f, v4 = 0.f;
        if (d >= 0) {
            size_t o = cbase + (size_t)d * HWv;
            v0 = c0[o]; v1 = c1[o]; v2 = c2[o]; v3 = c3[o]; v4 = c4[o];
        }
        ring[0][m][w] = v0; ring[1][m][w] = v1; ring[2][m][w] = v2;
        ring[3][m][w] = v3; ring[4][m][w] = v4;
        s0 += v0; s1 += v1; s2 += v2; s3 += v3; s4 += v4;
    }

    float local = 0.f;
    const float inv_k = 1.0f / K_SUM;

#pragma unroll 8
    for (int t = 0; t < 48; t++) {
        int d = d0 + t;
        size_t o = cbase + (size_t)d * HWv;

        // Leading edge (plane d+4).
        float l0 = 0.f, l1 = 0.f, l2 = 0.f, l3 = 0.f, l4 = 0.f;
        if (d + 4 < Dv) {
            size_t ol = o + 4 * (size_t)HWv;
            l0 = c0[ol]; l1 = c1[ol]; l2 = c2[ol]; l3 = c3[ol]; l4 = c4[ol];
        }
        s0 += l0; s1 += l1; s2 += l2; s3 += l3; s4 += l4;

        float iv = I[o];
        float jv = J[o];
        float iu = iv * inv_k;
        float ju = jv * inv_k;

        float cross = s4 - s0 * ju - s1 * iu + iu * ju * K_SUM;
        float ivar  = s2 - 2.f * s0 * iu + iu * iu * K_SUM;
        float jvar  = s3 - 2.f * s1 * ju + ju * ju * K_SUM;

        local += (cross * cross) / (ivar * jvar + 1e-5f);

        // Trailing edge (plane d-4) from smem ring; then recycle the slot.
        int slot = t & 7;
        s0 -= ring[0][slot][w]; s1 -= ring[1][slot][w];
        s2 -= ring[2][slot][w]; s3 -= ring[3][slot][w];
        s4 -= ring[4][slot][w];
        ring[0][slot][w] = l0; ring[1][slot][w] = l1; ring[2][slot][w] = l2;
        ring[3][slot][w] = l3; ring[4][slot][w] = l4;
    }

    // Reduce 192 threads -> 1 double atomic.
    __shared__ float red[6];
    float v = local;
#pragma unroll
    for (int off = 16; off > 0; off >>= 1)
        v += __shfl_down_sync(0xffffffffu, v, off);
    if ((w & 31) == 0) red[w >> 5] = v;
    __syncthreads();
    if (w == 0) {
        float s = 0.f;
#pragma unroll
        for (int i = 0; i < 6; i++) s += red[i];
        atomicAdd(&g_acc, (double)s);
    }
}

__global__ void finalize_k(float* __restrict__ out) {
    out[0] = (float)(-g_acc / (double)Nv);
}

extern "C" void kernel_launch(void* const* d_in, const int* in_sizes, int n_in,
                              void* d_out, int out_size) {
    const float* I = (const float*)d_in[0];
    const float* J = (const float*)d_in[1];
    float* out = (float*)d_out;

    const int p12_smem = (5 * HROWS * Wv + 8 * Wv) * (int)sizeof(float); // 98304
    cudaFuncSetAttribute(p12_k, cudaFuncAttributeMaxDynamicSharedMemorySize, p12_smem);

    zero_acc_k<<<1, 1>>>();
    p12_k<<<Bv * Dv * HTILES, 192, p12_smem>>>(I, J);   // 4608 blocks
    pass3_k<<<Bv * Hv * 4, 192>>>(I, J);                // 1536 blocks
    finalize_k<<<1, 1>>>(out);
}